// round 1
// baseline (speedup 1.0000x reference)
#include <cuda_runtime.h>
#include <math.h>

// Problem dims (fixed by the reference)
#define BB   8
#define TT   2048
#define NF   1024
#define BT   (BB*TT)          // 16384 rows
#define TOTAL ((size_t)BT*NF) // 16,777,216 elements per activation buffer

// Scratch activation buffers (allocation-free per harness rules)
__device__ float g_wi[BT*NF];   // raw  x@wi^T ; later overwritten with z = softsign(h)*og
__device__ float g_wig[BT*NF];  // sigmoid(x@wig^T + b)
__device__ float g_r[BT*NF];    // sigmoid(x@wr^T + b)
__device__ float g_og[BT*NF];   // sigmoid(x@wog^T + b)

__device__ __forceinline__ float sigf(float v) {
    return 1.0f / (1.0f + __expf(-v));
}

// ---------------------------------------------------------------------------
// SGEMM:  C[i, j] = sum_k A[i, k] * B[j, k]
//   A: [M_, K] row-major (K contiguous)  -- activations
//   B: [N_, K] row-major (K contiguous)  -- torch-style Linear weight
// MODE 0: store raw accumulator
// MODE 1: store sigmoid(acc + bias[j])
// Block tile 128x128, K-tile 8, 256 threads, 8x8 per thread.
// ---------------------------------------------------------------------------
template <int MODE>
__global__ void __launch_bounds__(256, 2)
sgemm_kernel(const float* __restrict__ A,
             const float* __restrict__ B,
             const float* __restrict__ bias,
             float* __restrict__ C,
             int M_, int N_, int K)
{
    const int BM = 128, BN = 128, BK = 8;
    __shared__ float As[BK][BM];
    __shared__ float Bs[BK][BN];

    const int bm = blockIdx.y * BM;
    const int bn = blockIdx.x * BN;
    const int tid = threadIdx.x;
    const int tx = tid & 15;       // 0..15 -> col group
    const int ty = tid >> 4;       // 0..15 -> row group

    // gmem load mapping: 1024 floats/tile = 256 float4 -> 1 per thread
    const int l_row  = tid >> 1;          // 0..127
    const int l_col4 = (tid & 1) * 4;     // 0 or 4

    const float* Aptr = A + (size_t)(bm + l_row) * K + l_col4;
    const float* Bptr = B + (size_t)(bn + l_row) * K + l_col4;

    float acc[8][8];
#pragma unroll
    for (int i = 0; i < 8; i++)
#pragma unroll
        for (int j = 0; j < 8; j++) acc[i][j] = 0.0f;

    const int nk = K / BK;

    float4 aReg = *(const float4*)Aptr;
    float4 bReg = *(const float4*)Bptr;

    for (int kt = 0; kt < nk; kt++) {
        // stage current regs into smem (transposed: [k][row])
        As[l_col4 + 0][l_row] = aReg.x;
        As[l_col4 + 1][l_row] = aReg.y;
        As[l_col4 + 2][l_row] = aReg.z;
        As[l_col4 + 3][l_row] = aReg.w;
        Bs[l_col4 + 0][l_row] = bReg.x;
        Bs[l_col4 + 1][l_row] = bReg.y;
        Bs[l_col4 + 2][l_row] = bReg.z;
        Bs[l_col4 + 3][l_row] = bReg.w;
        __syncthreads();

        if (kt + 1 < nk) {
            Aptr += BK;
            Bptr += BK;
            aReg = *(const float4*)Aptr;
            bReg = *(const float4*)Bptr;
        }

#pragma unroll
        for (int k = 0; k < BK; k++) {
            float4 a0 = *(const float4*)&As[k][ty * 8 + 0];
            float4 a1 = *(const float4*)&As[k][ty * 8 + 4];
            float4 b0 = *(const float4*)&Bs[k][tx * 8 + 0];
            float4 b1 = *(const float4*)&Bs[k][tx * 8 + 4];
            float a[8] = {a0.x, a0.y, a0.z, a0.w, a1.x, a1.y, a1.z, a1.w};
            float b[8] = {b0.x, b0.y, b0.z, b0.w, b1.x, b1.y, b1.z, b1.w};
#pragma unroll
            for (int i = 0; i < 8; i++)
#pragma unroll
                for (int j = 0; j < 8; j++)
                    acc[i][j] = fmaf(a[i], b[j], acc[i][j]);
        }
        __syncthreads();
    }

    // epilogue
#pragma unroll
    for (int i = 0; i < 8; i++) {
        const int row = bm + ty * 8 + i;
        float* crow = C + (size_t)row * N_ + bn + tx * 8;
#pragma unroll
        for (int j = 0; j < 8; j++) {
            float c = acc[i][j];
            if (MODE == 1) c = sigf(c + bias[bn + tx * 8 + j]);
            crow[j] = c;
        }
    }
}

// ---------------------------------------------------------------------------
// Scan: per-channel (b, m) linear recurrence over t:
//   h_t = h_{t-1} * r_t + wi_t * wig_t
//   z_t = softsign(h_t) * og_t          (written in place into g_wi)
//   mem_out = h_{T-1}
// 8192 channels, coalesced across m.
// ---------------------------------------------------------------------------
__global__ void scan_kernel(const float* __restrict__ mem0,
                            float* __restrict__ mem_out)
{
    const int c = blockIdx.x * blockDim.x + threadIdx.x;  // 0..8191
    if (c >= BB * NF) return;
    const int b = c >> 10;       // /1024
    const int m = c & (NF - 1);

    float h = mem0[c];
    size_t idx = (size_t)b * TT * NF + m;

#pragma unroll 4
    for (int t = 0; t < TT; t++) {
        const float wi = g_wi[idx];
        const float wg = g_wig[idx];
        const float r  = g_r[idx];
        const float og = g_og[idx];
        h = fmaf(h, r, wi * wg);
        const float z = (h / (1.0f + fabsf(h))) * og;
        g_wi[idx] = z;
        idx += NF;
    }
    mem_out[c] = h;
}

// ---------------------------------------------------------------------------
// Launch
// Input order: x, mem, wr_w, wr_b, wi_w, wig_w, wig_b, wog_w, wog_b, wo_w
// Output: y [8,2048,1024] f32, then mem_out [8,1024] f32 (concatenated)
// ---------------------------------------------------------------------------
extern "C" void kernel_launch(void* const* d_in, const int* in_sizes, int n_in,
                              void* d_out, int out_size)
{
    const float* x     = (const float*)d_in[0];
    const float* mem0  = (const float*)d_in[1];
    const float* wr_w  = (const float*)d_in[2];
    const float* wr_b  = (const float*)d_in[3];
    const float* wi_w  = (const float*)d_in[4];
    const float* wig_w = (const float*)d_in[5];
    const float* wig_b = (const float*)d_in[6];
    const float* wog_w = (const float*)d_in[7];
    const float* wog_b = (const float*)d_in[8];
    const float* wo_w  = (const float*)d_in[9];

    float* y       = (float*)d_out;            // [BT, NF]
    float* mem_out = y + TOTAL;                // [BB, NF]

    float *p_wi, *p_wig, *p_r, *p_og;
    cudaGetSymbolAddress((void**)&p_wi,  g_wi);
    cudaGetSymbolAddress((void**)&p_wig, g_wig);
    cudaGetSymbolAddress((void**)&p_r,   g_r);
    cudaGetSymbolAddress((void**)&p_og,  g_og);

    dim3 grid(NF / 128, BT / 128);   // (8, 128)
    dim3 blk(256);

    sgemm_kernel<1><<<grid, blk>>>(x, wr_w,  wr_b,  p_r,   BT, NF, NF);
    sgemm_kernel<1><<<grid, blk>>>(x, wig_w, wig_b, p_wig, BT, NF, NF);
    sgemm_kernel<1><<<grid, blk>>>(x, wog_w, wog_b, p_og,  BT, NF, NF);
    sgemm_kernel<0><<<grid, blk>>>(x, wi_w,  nullptr, p_wi, BT, NF, NF);

    scan_kernel<<<(BB * NF) / 256, 256>>>(mem0, mem_out);

    // y = z @ wo^T   (z lives in g_wi after the scan)
    sgemm_kernel<0><<<grid, blk>>>(p_wi, wo_w, nullptr, y, BT, NF, NF);
}

// round 2
// speedup vs baseline: 2.4713x; 2.4713x over previous
#include <cuda_runtime.h>
#include <cuda_bf16.h>
#include <math.h>
#include <stdint.h>

#define BB 8
#define TT 2048
#define NF 1024
#define BT (BB*TT)            // 16384
#define KSPLIT (3*NF)         // 3072

// ---------------- scratch (device globals; no allocs allowed) ----------------
__device__ float g_wi [(size_t)BT*NF];
__device__ float g_wig[(size_t)BT*NF];
__device__ float g_r  [(size_t)BT*NF];
__device__ float g_og [(size_t)BT*NF];
__device__ __nv_bfloat16 g_x2[(size_t)BT*KSPLIT];      // x split [hi|hi|lo]
__device__ __nv_bfloat16 g_z2[(size_t)BT*KSPLIT];      // z split [hi|hi|lo]
__device__ __nv_bfloat16 g_w2[5][(size_t)NF*KSPLIT];   // weights split [hi|lo|hi]

__device__ __forceinline__ float sigf(float v) {
    return 1.0f / (1.0f + __expf(-v));
}

// ---------------------------------------------------------------------------
// Split fp32 -> bf16 (hi, lo) into K'=3072 layout.
// varB=0 (activations): segments [hi | hi | lo]
// varB=1 (weights):     segments [hi | lo | hi]
// so dot(A2,B2) = hi*hi + hi*lo + lo*hi  (drops only lo*lo ~ 2^-16 rel)
// ---------------------------------------------------------------------------
__global__ void split_kernel(const float* __restrict__ in,
                             __nv_bfloat16* __restrict__ out,
                             int total, int varB)
{
    int idx = blockIdx.x * blockDim.x + threadIdx.x;
    if (idx >= total) return;
    int r = idx >> 10;          // /NF
    int c = idx & (NF - 1);
    float v = in[idx];
    __nv_bfloat16 hi = __float2bfloat16(v);
    __nv_bfloat16 lo = __float2bfloat16(v - __bfloat162float(hi));
    size_t base = (size_t)r * KSPLIT + c;
    out[base]          = hi;
    out[base + NF]     = varB ? lo : hi;
    out[base + 2*NF]   = varB ? hi : lo;
}

// ---------------------------------------------------------------------------
// bf16 tensor-core GEMM:  C[i,j] = sum_k A[i,k]*B[j,k]   (both K-contiguous)
// 128x128 tile, BK=32, 256 threads (8 warps as 2m x 4n, 64x32 per warp),
// cp.async double-buffered smem, ldmatrix fragments, mma.m16n8k16 bf16.
// MODE 0: raw fp32 store.  MODE 1: sigmoid(acc + bias[j]).
// ---------------------------------------------------------------------------
#define GBM 128
#define GBN 128
#define GBK 32
#define LDS 40   // padded halves per smem row (80B): conflict-free ldmatrix

__device__ __forceinline__ uint32_t smem_u32(const void* p) {
    return (uint32_t)__cvta_generic_to_shared(p);
}

#define MMA_BF16(d, a, b)                                              \
    asm volatile(                                                      \
        "mma.sync.aligned.m16n8k16.row.col.f32.bf16.bf16.f32 "         \
        "{%0,%1,%2,%3},{%4,%5,%6,%7},{%8,%9},{%0,%1,%2,%3};\n"         \
        : "+f"(d[0]), "+f"(d[1]), "+f"(d[2]), "+f"(d[3])               \
        : "r"(a[0]), "r"(a[1]), "r"(a[2]), "r"(a[3]),                  \
          "r"(b[0]), "r"(b[1]))

template <int MODE>
__global__ void __launch_bounds__(256, 2)
bgemm_kernel(const __nv_bfloat16* __restrict__ A,
             const __nv_bfloat16* __restrict__ B,
             const float* __restrict__ bias,
             float* __restrict__ C,
             int N_, int K)
{
    __shared__ __align__(16) __nv_bfloat16 sA[2][GBM * LDS];
    __shared__ __align__(16) __nv_bfloat16 sB[2][GBN * LDS];

    const int tid  = threadIdx.x;
    const int warp = tid >> 5, lane = tid & 31;
    const int wm = warp >> 2, wn = warp & 3;    // 2 x 4 warp grid
    const int bm = blockIdx.y * GBM;
    const int bn = blockIdx.x * GBN;

    float acc[4][4][4];
#pragma unroll
    for (int i = 0; i < 4; i++)
#pragma unroll
        for (int j = 0; j < 4; j++)
#pragma unroll
            for (int q = 0; q < 4; q++) acc[i][j][q] = 0.0f;

    // gmem->smem: per tile 128 rows x 64B = 512 16B-chunks; 2 per thread
    const int ca0 = tid, ca1 = tid + 256;
    const int r0 = ca0 >> 2, q0 = ca0 & 3;
    const int r1 = ca1 >> 2, q1 = ca1 & 3;

    const int nk = K / GBK;

#define LOAD_STAGE(kt, buf)                                                      \
    do {                                                                         \
        int k0 = (kt) * GBK;                                                     \
        const __nv_bfloat16* ga0 = A + (size_t)(bm + r0) * K + k0 + q0 * 8;      \
        const __nv_bfloat16* ga1 = A + (size_t)(bm + r1) * K + k0 + q1 * 8;      \
        const __nv_bfloat16* gb0 = B + (size_t)(bn + r0) * K + k0 + q0 * 8;      \
        const __nv_bfloat16* gb1 = B + (size_t)(bn + r1) * K + k0 + q1 * 8;      \
        uint32_t sa0 = smem_u32(&sA[buf][r0 * LDS + q0 * 8]);                    \
        uint32_t sa1 = smem_u32(&sA[buf][r1 * LDS + q1 * 8]);                    \
        uint32_t sb0 = smem_u32(&sB[buf][r0 * LDS + q0 * 8]);                    \
        uint32_t sb1 = smem_u32(&sB[buf][r1 * LDS + q1 * 8]);                    \
        asm volatile("cp.async.cg.shared.global [%0],[%1],16;\n" ::"r"(sa0),"l"(ga0)); \
        asm volatile("cp.async.cg.shared.global [%0],[%1],16;\n" ::"r"(sa1),"l"(ga1)); \
        asm volatile("cp.async.cg.shared.global [%0],[%1],16;\n" ::"r"(sb0),"l"(gb0)); \
        asm volatile("cp.async.cg.shared.global [%0],[%1],16;\n" ::"r"(sb1),"l"(gb1)); \
    } while (0)

    LOAD_STAGE(0, 0);
    asm volatile("cp.async.commit_group;\n");

    for (int kt = 0; kt < nk; kt++) {
        if (kt + 1 < nk) {
            LOAD_STAGE(kt + 1, (kt + 1) & 1);
            asm volatile("cp.async.commit_group;\n");
            asm volatile("cp.async.wait_group 1;\n");
        } else {
            asm volatile("cp.async.wait_group 0;\n");
        }
        __syncthreads();

        const __nv_bfloat16* a_s = sA[kt & 1];
        const __nv_bfloat16* b_s = sB[kt & 1];

#pragma unroll
        for (int ks = 0; ks < 2; ks++) {
            uint32_t af[4][4];
#pragma unroll
            for (int i = 0; i < 4; i++) {
                uint32_t addr = smem_u32(
                    &a_s[(wm * 64 + i * 16 + (lane & 15)) * LDS + ks * 16 + (lane >> 4) * 8]);
                asm volatile(
                    "ldmatrix.sync.aligned.m8n8.x4.shared.b16 {%0,%1,%2,%3},[%4];\n"
                    : "=r"(af[i][0]), "=r"(af[i][1]), "=r"(af[i][2]), "=r"(af[i][3])
                    : "r"(addr));
            }
            uint32_t bf[4][2];
#pragma unroll
            for (int g = 0; g < 2; g++) {
                uint32_t t0, t1, t2, t3;
                uint32_t addr = smem_u32(
                    &b_s[(wn * 32 + g * 16 + (lane & 15)) * LDS + ks * 16 + (lane >> 4) * 8]);
                asm volatile(
                    "ldmatrix.sync.aligned.m8n8.x4.shared.b16 {%0,%1,%2,%3},[%4];\n"
                    : "=r"(t0), "=r"(t1), "=r"(t2), "=r"(t3)
                    : "r"(addr));
                bf[2*g][0]   = t0; bf[2*g][1]   = t2;
                bf[2*g+1][0] = t1; bf[2*g+1][1] = t3;
            }
#pragma unroll
            for (int i = 0; i < 4; i++)
#pragma unroll
                for (int j = 0; j < 4; j++)
                    MMA_BF16(acc[i][j], af[i], bf[j]);
        }
        __syncthreads();
    }

    // epilogue
    const int lr = lane >> 2;
    const int lc = (lane & 3) * 2;
#pragma unroll
    for (int i = 0; i < 4; i++) {
#pragma unroll
        for (int j = 0; j < 4; j++) {
            int row = bm + wm * 64 + i * 16 + lr;
            int col = bn + wn * 32 + j * 8 + lc;
            float v0 = acc[i][j][0], v1 = acc[i][j][1];
            float v2 = acc[i][j][2], v3 = acc[i][j][3];
            if (MODE == 1) {
                float b0 = bias[col], b1 = bias[col + 1];
                v0 = sigf(v0 + b0); v1 = sigf(v1 + b1);
                v2 = sigf(v2 + b0); v3 = sigf(v3 + b1);
            }
            float2* p0 = (float2*)&C[(size_t)row * N_ + col];
            float2* p1 = (float2*)&C[(size_t)(row + 8) * N_ + col];
            *p0 = make_float2(v0, v1);
            *p1 = make_float2(v2, v3);
        }
    }
}

// ---------------------------------------------------------------------------
// Scan: h_t = h_{t-1}*r_t + wi_t*wig_t ; z = softsign(h)*og, written directly
// in split-bf16 K'=3072 layout ([hi|hi|lo]) for the output GEMM.
// ---------------------------------------------------------------------------
__global__ void scan_kernel(const float* __restrict__ mem0,
                            float* __restrict__ mem_out)
{
    const int c = blockIdx.x * blockDim.x + threadIdx.x;
    if (c >= BB * NF) return;
    const int b = c >> 10;
    const int m = c & (NF - 1);

    float h = mem0[c];
    size_t idx  = (size_t)b * TT * NF + m;
    size_t zrow = (size_t)b * TT * KSPLIT + m;

#pragma unroll 4
    for (int t = 0; t < TT; t++) {
        const float wi = g_wi[idx];
        const float wg = g_wig[idx];
        const float r  = g_r[idx];
        const float og = g_og[idx];
        h = fmaf(h, r, wi * wg);
        const float z = (h / (1.0f + fabsf(h))) * og;
        __nv_bfloat16 hi = __float2bfloat16(z);
        __nv_bfloat16 lo = __float2bfloat16(z - __bfloat162float(hi));
        g_z2[zrow]          = hi;
        g_z2[zrow + NF]     = hi;
        g_z2[zrow + 2*NF]   = lo;
        idx  += NF;
        zrow += KSPLIT;
    }
    mem_out[c] = h;
}

// ---------------------------------------------------------------------------
// Launch. Inputs: x, mem, wr_w, wr_b, wi_w, wig_w, wig_b, wog_w, wog_b, wo_w
// Output: y [8,2048,1024] f32 then mem_out [8,1024] f32.
// ---------------------------------------------------------------------------
extern "C" void kernel_launch(void* const* d_in, const int* in_sizes, int n_in,
                              void* d_out, int out_size)
{
    const float* x     = (const float*)d_in[0];
    const float* mem0  = (const float*)d_in[1];
    const float* wr_w  = (const float*)d_in[2];
    const float* wr_b  = (const float*)d_in[3];
    const float* wi_w  = (const float*)d_in[4];
    const float* wig_w = (const float*)d_in[5];
    const float* wig_b = (const float*)d_in[6];
    const float* wog_w = (const float*)d_in[7];
    const float* wog_b = (const float*)d_in[8];
    const float* wo_w  = (const float*)d_in[9];

    float* y       = (float*)d_out;
    float* mem_out = y + (size_t)BT * NF;

    float *p_wi, *p_wig, *p_r, *p_og;
    __nv_bfloat16 *p_x2, *p_z2, *p_w2;
    cudaGetSymbolAddress((void**)&p_wi,  g_wi);
    cudaGetSymbolAddress((void**)&p_wig, g_wig);
    cudaGetSymbolAddress((void**)&p_r,   g_r);
    cudaGetSymbolAddress((void**)&p_og,  g_og);
    cudaGetSymbolAddress((void**)&p_x2,  g_x2);
    cudaGetSymbolAddress((void**)&p_z2,  g_z2);
    cudaGetSymbolAddress((void**)&p_w2,  g_w2);

    const size_t wstride = (size_t)NF * KSPLIT;
    __nv_bfloat16* w2_r   = p_w2 + 0 * wstride;
    __nv_bfloat16* w2_i   = p_w2 + 1 * wstride;
    __nv_bfloat16* w2_ig  = p_w2 + 2 * wstride;
    __nv_bfloat16* w2_og  = p_w2 + 3 * wstride;
    __nv_bfloat16* w2_o   = p_w2 + 4 * wstride;

    // 1. split conversions
    {
        int tot = BT * NF;
        split_kernel<<<(tot + 255) / 256, 256>>>(x, p_x2, tot, 0);
        int wt = NF * NF;
        int wb = (wt + 255) / 256;
        split_kernel<<<wb, 256>>>(wr_w,  w2_r,  wt, 1);
        split_kernel<<<wb, 256>>>(wi_w,  w2_i,  wt, 1);
        split_kernel<<<wb, 256>>>(wig_w, w2_ig, wt, 1);
        split_kernel<<<wb, 256>>>(wog_w, w2_og, wt, 1);
        split_kernel<<<wb, 256>>>(wo_w,  w2_o,  wt, 1);
    }

    // 2. four input projections (tensor-core, K'=3072)
    dim3 grid(NF / GBN, BT / GBM);   // (8, 128)
    dim3 blk(256);
    bgemm_kernel<1><<<grid, blk>>>(p_x2, w2_r,  wr_b,  p_r,   NF, KSPLIT);
    bgemm_kernel<1><<<grid, blk>>>(p_x2, w2_ig, wig_b, p_wig, NF, KSPLIT);
    bgemm_kernel<1><<<grid, blk>>>(p_x2, w2_og, wog_b, p_og,  NF, KSPLIT);
    bgemm_kernel<0><<<grid, blk>>>(p_x2, w2_i,  nullptr, p_wi, NF, KSPLIT);

    // 3. recurrence scan (emits z in split layout + mem_out)
    scan_kernel<<<(BB * NF) / 256, 256>>>(mem0, mem_out);

    // 4. output projection
    bgemm_kernel<0><<<grid, blk>>>(p_z2, w2_o, nullptr, y, NF, KSPLIT);
}

// round 5
// speedup vs baseline: 4.1353x; 1.6734x over previous
#include <cuda_runtime.h>
#include <cuda_fp16.h>
#include <math.h>
#include <stdint.h>

#define BB 8
#define TT 2048
#define NF 1024
#define BT (BB*TT)            // 16384
#define KK NF                 // GEMM K = 1024 (single-pass fp16)

// GEMM tiling
#define BM 256
#define BN 128
#define BK 32
#define LDSH 40               // padded halves per smem row (80B) -> conflict-free ldmatrix
#define STAGES 3
#define NKIT (KK/BK)          // 32

// ---------------- scratch (device globals; no allocs allowed) ----------------
__device__ float g_wi [(size_t)BT*NF];
__device__ float g_wig[(size_t)BT*NF];
__device__ float g_r  [(size_t)BT*NF];
__device__ float g_og [(size_t)BT*NF];
__device__ __half g_xh [(size_t)BT*NF];        // x  fp16
__device__ __half g_zh [(size_t)BT*NF];        // z  fp16 (scan output)
__device__ __half g_w4 [(size_t)4*NF*NF];      // proj weights fp16: r, i, ig, og
__device__ __half g_woh[(size_t)NF*NF];        // output weight fp16

__device__ __forceinline__ float sigf(float v) {
    return 1.0f / (1.0f + __expf(-v));
}
__device__ __forceinline__ uint32_t smem_u32(const void* p) {
    return (uint32_t)__cvta_generic_to_shared(p);
}

#define MMA_F16(d, a, b)                                               \
    asm volatile(                                                      \
        "mma.sync.aligned.m16n8k16.row.col.f32.f16.f16.f32 "           \
        "{%0,%1,%2,%3},{%4,%5,%6,%7},{%8,%9},{%0,%1,%2,%3};\n"         \
        : "+f"(d[0]), "+f"(d[1]), "+f"(d[2]), "+f"(d[3])               \
        : "r"(a[0]), "r"(a[1]), "r"(a[2]), "r"(a[3]),                  \
          "r"(b[0]), "r"(b[1]))

#define LDMX4(r0, r1, r2, r3, addr)                                            \
    asm volatile("ldmatrix.sync.aligned.m8n8.x4.shared.b16 {%0,%1,%2,%3},[%4];\n" \
                 : "=r"(r0), "=r"(r1), "=r"(r2), "=r"(r3) : "r"(addr))

#define CPASYNC16(dst, src) \
    asm volatile("cp.async.cg.shared.global [%0],[%1],16;\n" ::"r"(dst), "l"(src))

struct EpiArgs {
    float* out[4];
    const float* bias[4];
};

// ---------------------------------------------------------------------------
// fp16 HMMA GEMM: C[i,j] = sum_k A[i,k]*B[j,k]
//   A: [M, 1024] fp16 row-major, B: [N_, 1024] fp16 row-major.
// Block 256x128x32, 256 thr, 8 warps (4m x 2n) of 64x64 each.
// 3-stage cp.async pipeline, register double-buffered ldmatrix fragments.
// Epilogue routed per 1024-col segment: bias!=null -> sigmoid(acc+bias).
// ---------------------------------------------------------------------------
template <int MODE>
__global__ void __launch_bounds__(256, 1)
hgemm_kernel(const __half* __restrict__ A,
             const __half* __restrict__ B,
             EpiArgs ea, int N_)
{
    extern __shared__ __align__(16) __half smh[];
    __half* sA = smh;                         // STAGES * BM*LDSH
    __half* sB = smh + STAGES * BM * LDSH;    // STAGES * BN*LDSH

    const int tid  = threadIdx.x;
    const int warp = tid >> 5, lane = tid & 31;
    const int wm = warp >> 1, wn = warp & 1;  // 4 x 2 warps of 64x64
    const int bm = blockIdx.y * BM;
    const int bn = blockIdx.x * BN;

    float acc[4][8][4];
#pragma unroll
    for (int i = 0; i < 4; i++)
#pragma unroll
        for (int j = 0; j < 8; j++)
#pragma unroll
            for (int q = 0; q < 4; q++) acc[i][j][q] = 0.0f;

    // gmem->smem mapping: 16B chunks; A: 1024 chunks (256r x 4), B: 512 (128r x 4)
    const int crow = tid >> 2;                // 0..63
    const int cq   = (tid & 3) * 8;           // halves offset 0/8/16/24

#define LOAD_STAGE(kt, s)                                                        \
    do {                                                                         \
        const int k0 = (kt) * BK;                                                \
        _Pragma("unroll")                                                        \
        for (int u = 0; u < 4; u++) {                                            \
            const int r = crow + u * 64;                                         \
            CPASYNC16(smem_u32(&sA[(size_t)(s) * BM * LDSH + r * LDSH + cq]),    \
                      A + (size_t)(bm + r) * KK + k0 + cq);                      \
        }                                                                        \
        _Pragma("unroll")                                                        \
        for (int u = 0; u < 2; u++) {                                            \
            const int r = crow + u * 64;                                         \
            CPASYNC16(smem_u32(&sB[(size_t)(s) * BN * LDSH + r * LDSH + cq]),    \
                      B + (size_t)(bn + r) * KK + k0 + cq);                      \
        }                                                                        \
    } while (0)

    LOAD_STAGE(0, 0);
    asm volatile("cp.async.commit_group;\n");
    LOAD_STAGE(1, 1);
    asm volatile("cp.async.commit_group;\n");
    asm volatile("cp.async.wait_group 1;\n");
    __syncthreads();

    uint32_t af[2][4][4], bf[2][8][2];

    // fragment load helpers (ks = 0/1 -> k16 half of the 32-wide stage)
#define LDFRAG(buf, s, ks)                                                        \
    do {                                                                          \
        const __half* a_s = &sA[(size_t)(s) * BM * LDSH];                         \
        const __half* b_s = &sB[(size_t)(s) * BN * LDSH];                         \
        _Pragma("unroll")                                                         \
        for (int i = 0; i < 4; i++) {                                             \
            uint32_t ad = smem_u32(                                               \
                &a_s[(wm * 64 + i * 16 + (lane & 15)) * LDSH + (ks) * 16 + (lane >> 4) * 8]); \
            LDMX4(af[buf][i][0], af[buf][i][1], af[buf][i][2], af[buf][i][3], ad); \
        }                                                                         \
        _Pragma("unroll")                                                         \
        for (int g = 0; g < 4; g++) {                                             \
            uint32_t t0, t1, t2, t3;                                              \
            uint32_t ad = smem_u32(                                               \
                &b_s[(wn * 64 + g * 16 + (lane & 15)) * LDSH + (ks) * 16 + (lane >> 4) * 8]); \
            LDMX4(t0, t1, t2, t3, ad);                                            \
            bf[buf][2*g][0]   = t0; bf[buf][2*g][1]   = t2;                       \
            bf[buf][2*g+1][0] = t1; bf[buf][2*g+1][1] = t3;                       \
        }                                                                         \
    } while (0)

#define DO_MMA(buf)                                                \
    do {                                                           \
        _Pragma("unroll")                                          \
        for (int i = 0; i < 4; i++)                                \
            _Pragma("unroll")                                      \
            for (int j = 0; j < 8; j++)                            \
                MMA_F16(acc[i][j], af[buf][i], bf[buf][j]);        \
    } while (0)

    LDFRAG(0, 0, 0);

#pragma unroll 1
    for (int kt = 0; kt < NKIT; kt++) {
        const int s = kt % STAGES;
        LDFRAG(1, s, 1);
        if (kt + 2 < NKIT) LOAD_STAGE(kt + 2, (kt + 2) % STAGES);
        asm volatile("cp.async.commit_group;\n");
        DO_MMA(0);
        asm volatile("cp.async.wait_group 1;\n");
        __syncthreads();
        LDFRAG(0, (kt + 1) % STAGES, 0);   // last iter: harmless stale read
        DO_MMA(1);
    }

    // ---- epilogue ----
    const int seg = bn >> 10;                  // 1024-col segment
    float* outp = ea.out[seg];
    const float* biasp = ea.bias[seg];
    const int lr = lane >> 2;
    const int lc = (lane & 3) * 2;

#pragma unroll
    for (int i = 0; i < 4; i++) {
#pragma unroll
        for (int j = 0; j < 8; j++) {
            const int row = bm + wm * 64 + i * 16 + lr;
            const int col = bn + wn * 64 + j * 8 + lc;
            const int colN = col & (NF - 1);
            float v0 = acc[i][j][0], v1 = acc[i][j][1];
            float v2 = acc[i][j][2], v3 = acc[i][j][3];
            if (MODE == 1 && biasp) {
                const float b0 = biasp[colN], b1 = biasp[colN + 1];
                v0 = sigf(v0 + b0); v1 = sigf(v1 + b1);
                v2 = sigf(v2 + b0); v3 = sigf(v3 + b1);
            }
            *(float2*)&outp[(size_t)row * NF + colN]       = make_float2(v0, v1);
            *(float2*)&outp[(size_t)(row + 8) * NF + colN] = make_float2(v2, v3);
        }
    }
}

// ---------------------------------------------------------------------------
// fp32 -> fp16 conversion (vectorized)
// ---------------------------------------------------------------------------
__global__ void conv_kernel(const float* __restrict__ in,
                            __half* __restrict__ out, int total4)
{
    int i = blockIdx.x * blockDim.x + threadIdx.x;
    if (i >= total4) return;
    float4 v = ((const float4*)in)[i];
    __half2 h0 = __floats2half2_rn(v.x, v.y);
    __half2 h1 = __floats2half2_rn(v.z, v.w);
    ((__half2*)out)[2*i]   = h0;
    ((__half2*)out)[2*i+1] = h1;
}

// ---------------------------------------------------------------------------
// Scan: h_t = h_{t-1}*r_t + wi_t*wig_t ; z = softsign(h)*og -> fp16
// ---------------------------------------------------------------------------
__global__ void scan_kernel(const float* __restrict__ mem0,
                            float* __restrict__ mem_out)
{
    const int c = blockIdx.x * blockDim.x + threadIdx.x;
    if (c >= BB * NF) return;
    const int b = c >> 10;
    const int m = c & (NF - 1);

    float h = mem0[c];
    size_t idx = (size_t)b * TT * NF + m;

#pragma unroll 4
    for (int t = 0; t < TT; t++) {
        const float wi = g_wi[idx];
        const float wg = g_wig[idx];
        const float r  = g_r[idx];
        const float og = g_og[idx];
        h = fmaf(h, r, wi * wg);
        const float z = (h / (1.0f + fabsf(h))) * og;
        g_zh[idx] = __float2half_rn(z);
        idx += NF;
    }
    mem_out[c] = h;
}

// ---------------------------------------------------------------------------
// Launch. Inputs: x, mem, wr_w, wr_b, wi_w, wig_w, wig_b, wog_w, wog_b, wo_w
// Output: y [8,2048,1024] f32 then mem_out [8,1024] f32.
// ---------------------------------------------------------------------------
extern "C" void kernel_launch(void* const* d_in, const int* in_sizes, int n_in,
                              void* d_out, int out_size)
{
    const float* x     = (const float*)d_in[0];
    const float* mem0  = (const float*)d_in[1];
    const float* wr_w  = (const float*)d_in[2];
    const float* wr_b  = (const float*)d_in[3];
    const float* wi_w  = (const float*)d_in[4];
    const float* wig_w = (const float*)d_in[5];
    const float* wig_b = (const float*)d_in[6];
    const float* wog_w = (const float*)d_in[7];
    const float* wog_b = (const float*)d_in[8];
    const float* wo_w  = (const float*)d_in[9];

    float* y       = (float*)d_out;
    float* mem_out = y + (size_t)BT * NF;

    float *p_wi, *p_wig, *p_r, *p_og;
    __half *p_xh, *p_zh, *p_w4, *p_woh;
    cudaGetSymbolAddress((void**)&p_wi,  g_wi);
    cudaGetSymbolAddress((void**)&p_wig, g_wig);
    cudaGetSymbolAddress((void**)&p_r,   g_r);
    cudaGetSymbolAddress((void**)&p_og,  g_og);
    cudaGetSymbolAddress((void**)&p_xh,  g_xh);
    cudaGetSymbolAddress((void**)&p_zh,  g_zh);
    cudaGetSymbolAddress((void**)&p_w4,  g_w4);
    cudaGetSymbolAddress((void**)&p_woh, g_woh);

    const size_t ws = (size_t)NF * NF;

    const int smem_bytes = STAGES * (BM + BN) * LDSH * sizeof(__half); // 92160
    cudaFuncSetAttribute(hgemm_kernel<0>, cudaFuncAttributeMaxDynamicSharedMemorySize, smem_bytes);
    cudaFuncSetAttribute(hgemm_kernel<1>, cudaFuncAttributeMaxDynamicSharedMemorySize, smem_bytes);

    // 1. fp32 -> fp16 conversions
    {
        int xt4 = (BT * NF) / 4;
        conv_kernel<<<(xt4 + 255) / 256, 256>>>(x, p_xh, xt4);
        int wt4 = (NF * NF) / 4;
        int wb = (wt4 + 255) / 256;
        conv_kernel<<<wb, 256>>>(wr_w,  p_w4 + 0 * ws, wt4);   // seg 0
        conv_kernel<<<wb, 256>>>(wi_w,  p_w4 + 1 * ws, wt4);   // seg 1
        conv_kernel<<<wb, 256>>>(wig_w, p_w4 + 2 * ws, wt4);   // seg 2
        conv_kernel<<<wb, 256>>>(wog_w, p_w4 + 3 * ws, wt4);   // seg 3
        conv_kernel<<<wb, 256>>>(wo_w,  p_woh,         wt4);
    }

    // 2. fused input projections: C[16384, 4096]
    {
        EpiArgs ea;
        ea.out[0] = p_r;   ea.bias[0] = wr_b;
        ea.out[1] = p_wi;  ea.bias[1] = nullptr;   // raw (no sigmoid)
        ea.out[2] = p_wig; ea.bias[2] = wig_b;
        ea.out[3] = p_og;  ea.bias[3] = wog_b;
        dim3 grid(4 * NF / BN, BT / BM);   // (32, 64)
        hgemm_kernel<1><<<grid, 256, smem_bytes>>>(p_xh, p_w4, ea, NF);
    }

    // 3. recurrence scan (emits fp16 z + mem_out)
    scan_kernel<<<(BB * NF) / 256, 256>>>(mem0, mem_out);

    // 4. output projection: y = z @ wo^T
    {
        EpiArgs ea;
        ea.out[0] = y;       ea.bias[0] = nullptr;
        ea.out[1] = nullptr; ea.bias[1] = nullptr;
        ea.out[2] = nullptr; ea.bias[2] = nullptr;
        ea.out[3] = nullptr; ea.bias[3] = nullptr;
        dim3 grid(NF / BN, BT / BM);       // (8, 64)
        hgemm_kernel<0><<<grid, 256, smem_bytes>>>(p_zh, p_woh, ea, NF);
    }
}

// round 8
// speedup vs baseline: 4.3704x; 1.0568x over previous
#include <cuda_runtime.h>
#include <cuda_fp16.h>
#include <math.h>
#include <stdint.h>

#define BB 8
#define TT 2048
#define NF 1024
#define BT (BB*TT)            // 16384
#define KK NF                 // GEMM K = 1024

// GEMM tiling: 128x128x32 block, 128 threads, 4 warps (2x2) of 64x64
#define BM 128
#define BN 128
#define BK 32
#define LDSH 40               // padded halves per smem row (80B) -> conflict-free ldmatrix
#define STAGES 4
#define NKIT (KK/BK)          // 32
#define SMEM_BYTES (STAGES*(BM+BN)*LDSH*2)   // 81920

// ---------------- scratch (device globals; no allocs allowed) ----------------
__device__ float g_wi [(size_t)BT*NF];
__device__ float g_wig[(size_t)BT*NF];
__device__ float g_r  [(size_t)BT*NF];
__device__ float g_og [(size_t)BT*NF];
__device__ __half g_xh [(size_t)BT*NF];        // x  fp16
__device__ __half g_zh [(size_t)BT*NF];        // z  fp16 (scan output)
__device__ __half g_w4 [(size_t)4*NF*NF];      // proj weights fp16: r, i, ig, og
__device__ __half g_woh[(size_t)NF*NF];        // output weight fp16

__device__ __forceinline__ float sigf(float v) {
    return 1.0f / (1.0f + __expf(-v));
}
__device__ __forceinline__ uint32_t smem_u32(const void* p) {
    return (uint32_t)__cvta_generic_to_shared(p);
}

#define MMA_F16(d, a, b)                                               \
    asm volatile(                                                      \
        "mma.sync.aligned.m16n8k16.row.col.f32.f16.f16.f32 "           \
        "{%0,%1,%2,%3},{%4,%5,%6,%7},{%8,%9},{%0,%1,%2,%3};\n"         \
        : "+f"(d[0]), "+f"(d[1]), "+f"(d[2]), "+f"(d[3])               \
        : "r"(a[0]), "r"(a[1]), "r"(a[2]), "r"(a[3]),                  \
          "r"(b[0]), "r"(b[1]))

#define LDMX4(r0, r1, r2, r3, addr)                                            \
    asm volatile("ldmatrix.sync.aligned.m8n8.x4.shared.b16 {%0,%1,%2,%3},[%4];\n" \
                 : "=r"(r0), "=r"(r1), "=r"(r2), "=r"(r3) : "r"(addr))

#define CPASYNC16(dst, src) \
    asm volatile("cp.async.cg.shared.global [%0],[%1],16;\n" ::"r"(dst), "l"(src))

struct EpiArgs {
    float* out[4];
    const float* bias[4];
};

// ---------------------------------------------------------------------------
// fp16 HMMA GEMM: C[i,j] = sum_k A[i,k]*B[j,k]
//   A: [M, 1024] fp16 row-major, B: [N_, 1024] fp16 row-major.
// 128x128x32 block, 128 thr, 4 warps (2m x 2n) of 64x64.
// 4-stage cp.async pipeline, register double-buffered ldmatrix fragments.
// Epilogue routed per 1024-col segment: bias!=null -> sigmoid(acc+bias).
// ---------------------------------------------------------------------------
__global__ void __launch_bounds__(128, 2)
hgemm_kernel(const __half* __restrict__ A,
             const __half* __restrict__ B,
             EpiArgs ea)
{
    extern __shared__ __align__(16) __half smh[];
    __half* sA = smh;                         // STAGES * BM*LDSH
    __half* sB = smh + STAGES * BM * LDSH;    // STAGES * BN*LDSH

    const int tid  = threadIdx.x;
    const int warp = tid >> 5, lane = tid & 31;
    const int wm = warp >> 1, wn = warp & 1;  // 2 x 2 warps of 64x64
    const int bm = blockIdx.y * BM;
    const int bn = blockIdx.x * BN;

    float acc[4][8][4];
#pragma unroll
    for (int i = 0; i < 4; i++)
#pragma unroll
        for (int j = 0; j < 8; j++)
#pragma unroll
            for (int q = 0; q < 4; q++) acc[i][j][q] = 0.0f;

    // gmem->smem mapping: 16B chunks; A: 512 chunks (128r x 4), B: 512
    const int crow = tid >> 2;                // 0..31
    const int cq   = (tid & 3) * 8;           // halves offset 0/8/16/24

#define LOAD_STAGE(kt, s)                                                        \
    do {                                                                         \
        const int k0 = (kt) * BK;                                                \
        _Pragma("unroll")                                                        \
        for (int u = 0; u < 4; u++) {                                            \
            const int r = crow + u * 32;                                         \
            CPASYNC16(smem_u32(&sA[(size_t)(s) * BM * LDSH + r * LDSH + cq]),    \
                      A + (size_t)(bm + r) * KK + k0 + cq);                      \
            CPASYNC16(smem_u32(&sB[(size_t)(s) * BN * LDSH + r * LDSH + cq]),    \
                      B + (size_t)(bn + r) * KK + k0 + cq);                      \
        }                                                                        \
    } while (0)

    LOAD_STAGE(0, 0);
    asm volatile("cp.async.commit_group;\n");
    LOAD_STAGE(1, 1);
    asm volatile("cp.async.commit_group;\n");
    LOAD_STAGE(2, 2);
    asm volatile("cp.async.commit_group;\n");
    asm volatile("cp.async.wait_group 2;\n");
    __syncthreads();

    uint32_t af[2][4][4], bf[2][8][2];

#define LDFRAG(buf, s, ks)                                                        \
    do {                                                                          \
        const __half* a_s = &sA[(size_t)(s) * BM * LDSH];                         \
        const __half* b_s = &sB[(size_t)(s) * BN * LDSH];                         \
        _Pragma("unroll")                                                         \
        for (int i = 0; i < 4; i++) {                                             \
            uint32_t ad = smem_u32(                                               \
                &a_s[(wm * 64 + i * 16 + (lane & 15)) * LDSH + (ks) * 16 + (lane >> 4) * 8]); \
            LDMX4(af[buf][i][0], af[buf][i][1], af[buf][i][2], af[buf][i][3], ad); \
        }                                                                         \
        _Pragma("unroll")                                                         \
        for (int g = 0; g < 4; g++) {                                             \
            uint32_t t0, t1, t2, t3;                                              \
            uint32_t ad = smem_u32(                                               \
                &b_s[(wn * 64 + g * 16 + (lane & 15)) * LDSH + (ks) * 16 + (lane >> 4) * 8]); \
            LDMX4(t0, t1, t2, t3, ad);                                            \
            bf[buf][2*g][0]   = t0; bf[buf][2*g][1]   = t2;                       \
            bf[buf][2*g+1][0] = t1; bf[buf][2*g+1][1] = t3;                       \
        }                                                                         \
    } while (0)

#define DO_MMA(buf)                                                \
    do {                                                           \
        _Pragma("unroll")                                          \
        for (int i = 0; i < 4; i++)                                \
            _Pragma("unroll")                                      \
            for (int j = 0; j < 8; j++)                            \
                MMA_F16(acc[i][j], af[buf][i], bf[buf][j]);        \
    } while (0)

    LDFRAG(0, 0, 0);

#pragma unroll 1
    for (int kt = 0; kt < NKIT; kt++) {
        const int s = kt % STAGES;
        LDFRAG(1, s, 1);
        if (kt + 3 < NKIT) LOAD_STAGE(kt + 3, (kt + 3) % STAGES);
        asm volatile("cp.async.commit_group;\n");       // empty group ok: keeps count aligned
        DO_MMA(0);
        asm volatile("cp.async.wait_group 2;\n");       // stage kt+1 resident
        __syncthreads();
        LDFRAG(0, (kt + 1) % STAGES, 0);                // last iter: harmless stale read
        DO_MMA(1);
    }

    // ---- epilogue ----
    const int seg = bn >> 10;                  // 1024-col segment
    float* outp = ea.out[seg];
    const float* biasp = ea.bias[seg];
    const int lr = lane >> 2;
    const int lc = (lane & 3) * 2;

#pragma unroll
    for (int i = 0; i < 4; i++) {
#pragma unroll
        for (int j = 0; j < 8; j++) {
            const int row = bm + wm * 64 + i * 16 + lr;
            const int col = bn + wn * 64 + j * 8 + lc;
            const int colN = col & (NF - 1);
            float v0 = acc[i][j][0], v1 = acc[i][j][1];
            float v2 = acc[i][j][2], v3 = acc[i][j][3];
            if (biasp) {
                const float b0 = biasp[colN], b1 = biasp[colN + 1];
                v0 = sigf(v0 + b0); v1 = sigf(v1 + b1);
                v2 = sigf(v2 + b0); v3 = sigf(v3 + b1);
            }
            *(float2*)&outp[(size_t)row * NF + colN]       = make_float2(v0, v1);
            *(float2*)&outp[(size_t)(row + 8) * NF + colN] = make_float2(v2, v3);
        }
    }
}

// ---------------------------------------------------------------------------
// fp32 -> fp16 conversions (vectorized). conv2 handles two tensors per launch
// so the fused GEMM lands on launch index 5 (ncu -s 5 profiles it).
// ---------------------------------------------------------------------------
__global__ void conv_kernel(const float* __restrict__ in,
                            __half* __restrict__ out, int total4)
{
    int i = blockIdx.x * blockDim.x + threadIdx.x;
    if (i >= total4) return;
    float4 v = ((const float4*)in)[i];
    ((__half2*)out)[2*i]   = __floats2half2_rn(v.x, v.y);
    ((__half2*)out)[2*i+1] = __floats2half2_rn(v.z, v.w);
}

__global__ void conv2_kernel(const float* __restrict__ inA, __half* __restrict__ outA,
                             const float* __restrict__ inB, __half* __restrict__ outB,
                             int total4)
{
    int i = blockIdx.x * blockDim.x + threadIdx.x;
    if (i >= total4) return;
    float4 v = ((const float4*)inA)[i];
    ((__half2*)outA)[2*i]   = __floats2half2_rn(v.x, v.y);
    ((__half2*)outA)[2*i+1] = __floats2half2_rn(v.z, v.w);
    float4 w = ((const float4*)inB)[i];
    ((__half2*)outB)[2*i]   = __floats2half2_rn(w.x, w.y);
    ((__half2*)outB)[2*i+1] = __floats2half2_rn(w.z, w.w);
}

// ---------------------------------------------------------------------------
// Scan: h_t = h_{t-1}*r_t + wi_t*wig_t ; z = softsign(h)*og -> fp16
// ---------------------------------------------------------------------------
__global__ void scan_kernel(const float* __restrict__ mem0,
                            float* __restrict__ mem_out)
{
    const int c = blockIdx.x * blockDim.x + threadIdx.x;
    if (c >= BB * NF) return;
    const int b = c >> 10;
    const int m = c & (NF - 1);

    float h = mem0[c];
    size_t idx = (size_t)b * TT * NF + m;

#pragma unroll 8
    for (int t = 0; t < TT; t++) {
        const float wi = g_wi[idx];
        const float wg = g_wig[idx];
        const float r  = g_r[idx];
        const float og = g_og[idx];
        h = fmaf(h, r, wi * wg);
        const float z = (h / (1.0f + fabsf(h))) * og;
        g_zh[idx] = __float2half_rn(z);
        idx += NF;
    }
    mem_out[c] = h;
}

// ---------------------------------------------------------------------------
// Launch. Inputs: x, mem, wr_w, wr_b, wi_w, wig_w, wig_b, wog_w, wog_b, wo_w
// Output: y [8,2048,1024] f32 then mem_out [8,1024] f32.
// ---------------------------------------------------------------------------
extern "C" void kernel_launch(void* const* d_in, const int* in_sizes, int n_in,
                              void* d_out, int out_size)
{
    const float* x     = (const float*)d_in[0];
    const float* mem0  = (const float*)d_in[1];
    const float* wr_w  = (const float*)d_in[2];
    const float* wr_b  = (const float*)d_in[3];
    const float* wi_w  = (const float*)d_in[4];
    const float* wig_w = (const float*)d_in[5];
    const float* wig_b = (const float*)d_in[6];
    const float* wog_w = (const float*)d_in[7];
    const float* wog_b = (const float*)d_in[8];
    const float* wo_w  = (const float*)d_in[9];

    float* y       = (float*)d_out;
    float* mem_out = y + (size_t)BT * NF;

    float *p_wi, *p_wig, *p_r, *p_og;
    __half *p_xh, *p_zh, *p_w4, *p_woh;
    cudaGetSymbolAddress((void**)&p_wi,  g_wi);
    cudaGetSymbolAddress((void**)&p_wig, g_wig);
    cudaGetSymbolAddress((void**)&p_r,   g_r);
    cudaGetSymbolAddress((void**)&p_og,  g_og);
    cudaGetSymbolAddress((void**)&p_xh,  g_xh);
    cudaGetSymbolAddress((void**)&p_zh,  g_zh);
    cudaGetSymbolAddress((void**)&p_w4,  g_w4);
    cudaGetSymbolAddress((void**)&p_woh, g_woh);

    const size_t ws = (size_t)NF * NF;

    cudaFuncSetAttribute(hgemm_kernel, cudaFuncAttributeMaxDynamicSharedMemorySize, SMEM_BYTES);

    // 1. conversions (exactly 5 launches; GEMM1 = launch #5 for ncu -s 5)
    {
        int wt4 = (NF * NF) / 4;
        int wb = (wt4 + 255) / 256;
        conv2_kernel<<<wb, 256>>>(wr_w,  p_w4 + 0 * ws, wi_w,  p_w4 + 1 * ws, wt4);   // 0
        conv2_kernel<<<wb, 256>>>(wig_w, p_w4 + 2 * ws, wog_w, p_w4 + 3 * ws, wt4);   // 1
        conv_kernel<<<wb, 256>>>(wo_w, p_woh, wt4);                                   // 2
        int xh4 = (BT * NF) / 8;    // half of x, in float4 units
        conv_kernel<<<(xh4 + 255) / 256, 256>>>(x, p_xh, xh4);                        // 3
        conv_kernel<<<(xh4 + 255) / 256, 256>>>(x + (size_t)4 * xh4,
                                                p_xh + (size_t)4 * xh4, xh4);         // 4
    }

    // 2. fused input projections: C[16384, 4096]                                     // 5
    {
        EpiArgs ea;
        ea.out[0] = p_r;   ea.bias[0] = wr_b;
        ea.out[1] = p_wi;  ea.bias[1] = nullptr;   // raw (no sigmoid)
        ea.out[2] = p_wig; ea.bias[2] = wig_b;
        ea.out[3] = p_og;  ea.bias[3] = wog_b;
        dim3 grid(4 * NF / BN, BT / BM);   // (32, 128)
        hgemm_kernel<<<grid, 128, SMEM_BYTES>>>(p_xh, p_w4, ea);
    }

    // 3. recurrence scan                                                             // 6
    scan_kernel<<<(BB * NF) / 256, 256>>>(mem0, mem_out);

    // 4. output projection: y = z @ wo^T                                             // 7
    {
        EpiArgs ea;
        ea.out[0] = y;       ea.bias[0] = nullptr;
        ea.out[1] = nullptr; ea.bias[1] = nullptr;
        ea.out[2] = nullptr; ea.bias[2] = nullptr;
        ea.out[3] = nullptr; ea.bias[3] = nullptr;
        dim3 grid(NF / BN, BT / BM);       // (8, 128)
        hgemm_kernel<<<grid, 128, SMEM_BYTES>>>(p_zh, p_woh, ea);
    }
}

// round 9
// speedup vs baseline: 9.8612x; 2.2564x over previous
#include <cuda_runtime.h>
#include <cuda_fp16.h>
#include <math.h>
#include <stdint.h>

#define BB 8
#define TT 2048
#define NF 1024
#define BT (BB*TT)            // 16384
#define KK NF                 // GEMM K = 1024
#define NCH 16                // scan chunks
#define CHT (TT/NCH)          // 128 timesteps per chunk
#define NCHAN (BB*NF)         // 8192 channels

// GEMM tiling: 128x128x32 block, 128 threads, 4 warps (2x2) of 64x64
#define BM 128
#define BN 128
#define BK 32
#define LDSH 40               // padded halves per smem row (80B) -> conflict-free ldmatrix
#define STAGES 4
#define NKIT (KK/BK)          // 32
#define SMEM_BYTES (STAGES*(BM+BN)*LDSH*2)   // 81920

// ---------------- scratch (device globals; no allocs allowed) ----------------
__device__ float g_wi [(size_t)BT*NF];
__device__ float g_wig[(size_t)BT*NF];
__device__ float g_r  [(size_t)BT*NF];
__device__ float g_og [(size_t)BT*NF];
__device__ __half g_xh [(size_t)BT*NF];        // x  fp16
__device__ __half g_zh [(size_t)BT*NF];        // z  fp16 (scan output)
__device__ __half g_w4 [(size_t)4*NF*NF];      // proj weights fp16: r, i, ig, og
__device__ __half g_woh[(size_t)NF*NF];        // output weight fp16
__device__ float g_sa [NCH*NCHAN];             // per-chunk prod(r)
__device__ float g_sb [NCH*NCHAN];             // per-chunk partial scan (h0=0)
__device__ float g_hs [NCH*NCHAN];             // per-chunk starting h

__device__ __forceinline__ float sigf(float v) {
    return 1.0f / (1.0f + __expf(-v));
}
__device__ __forceinline__ uint32_t smem_u32(const void* p) {
    return (uint32_t)__cvta_generic_to_shared(p);
}

#define MMA_F16(d, a, b)                                               \
    asm volatile(                                                      \
        "mma.sync.aligned.m16n8k16.row.col.f32.f16.f16.f32 "           \
        "{%0,%1,%2,%3},{%4,%5,%6,%7},{%8,%9},{%0,%1,%2,%3};\n"         \
        : "+f"(d[0]), "+f"(d[1]), "+f"(d[2]), "+f"(d[3])               \
        : "r"(a[0]), "r"(a[1]), "r"(a[2]), "r"(a[3]),                  \
          "r"(b[0]), "r"(b[1]))

#define LDMX4(r0, r1, r2, r3, addr)                                            \
    asm volatile("ldmatrix.sync.aligned.m8n8.x4.shared.b16 {%0,%1,%2,%3},[%4];\n" \
                 : "=r"(r0), "=r"(r1), "=r"(r2), "=r"(r3) : "r"(addr))

#define CPASYNC16(dst, src) \
    asm volatile("cp.async.cg.shared.global [%0],[%1],16;\n" ::"r"(dst), "l"(src))

struct EpiArgs {
    float* out[4];
    const float* bias[4];
};

// ---------------------------------------------------------------------------
// fp16 HMMA GEMM: C[i,j] = sum_k A[i,k]*B[j,k]
// 128x128x32 block, 128 thr, 4 warps (2m x 2n) of 64x64, 4-stage cp.async,
// register double-buffered ldmatrix fragments.
// ---------------------------------------------------------------------------
__global__ void __launch_bounds__(128, 2)
hgemm_kernel(const __half* __restrict__ A,
             const __half* __restrict__ B,
             EpiArgs ea)
{
    extern __shared__ __align__(16) __half smh[];
    __half* sA = smh;                         // STAGES * BM*LDSH
    __half* sB = smh + STAGES * BM * LDSH;    // STAGES * BN*LDSH

    const int tid  = threadIdx.x;
    const int warp = tid >> 5, lane = tid & 31;
    const int wm = warp >> 1, wn = warp & 1;  // 2 x 2 warps of 64x64
    const int bm = blockIdx.y * BM;
    const int bn = blockIdx.x * BN;

    float acc[4][8][4];
#pragma unroll
    for (int i = 0; i < 4; i++)
#pragma unroll
        for (int j = 0; j < 8; j++)
#pragma unroll
            for (int q = 0; q < 4; q++) acc[i][j][q] = 0.0f;

    const int crow = tid >> 2;                // 0..31
    const int cq   = (tid & 3) * 8;           // halves offset 0/8/16/24

#define LOAD_STAGE(kt, s)                                                        \
    do {                                                                         \
        const int k0 = (kt) * BK;                                                \
        _Pragma("unroll")                                                        \
        for (int u = 0; u < 4; u++) {                                            \
            const int r = crow + u * 32;                                         \
            CPASYNC16(smem_u32(&sA[(size_t)(s) * BM * LDSH + r * LDSH + cq]),    \
                      A + (size_t)(bm + r) * KK + k0 + cq);                      \
            CPASYNC16(smem_u32(&sB[(size_t)(s) * BN * LDSH + r * LDSH + cq]),    \
                      B + (size_t)(bn + r) * KK + k0 + cq);                      \
        }                                                                        \
    } while (0)

    LOAD_STAGE(0, 0);
    asm volatile("cp.async.commit_group;\n");
    LOAD_STAGE(1, 1);
    asm volatile("cp.async.commit_group;\n");
    LOAD_STAGE(2, 2);
    asm volatile("cp.async.commit_group;\n");
    asm volatile("cp.async.wait_group 2;\n");
    __syncthreads();

    uint32_t af[2][4][4], bf[2][8][2];

#define LDFRAG(buf, s, ks)                                                        \
    do {                                                                          \
        const __half* a_s = &sA[(size_t)(s) * BM * LDSH];                         \
        const __half* b_s = &sB[(size_t)(s) * BN * LDSH];                         \
        _Pragma("unroll")                                                         \
        for (int i = 0; i < 4; i++) {                                             \
            uint32_t ad = smem_u32(                                               \
                &a_s[(wm * 64 + i * 16 + (lane & 15)) * LDSH + (ks) * 16 + (lane >> 4) * 8]); \
            LDMX4(af[buf][i][0], af[buf][i][1], af[buf][i][2], af[buf][i][3], ad); \
        }                                                                         \
        _Pragma("unroll")                                                         \
        for (int g = 0; g < 4; g++) {                                             \
            uint32_t t0, t1, t2, t3;                                              \
            uint32_t ad = smem_u32(                                               \
                &b_s[(wn * 64 + g * 16 + (lane & 15)) * LDSH + (ks) * 16 + (lane >> 4) * 8]); \
            LDMX4(t0, t1, t2, t3, ad);                                            \
            bf[buf][2*g][0]   = t0; bf[buf][2*g][1]   = t2;                       \
            bf[buf][2*g+1][0] = t1; bf[buf][2*g+1][1] = t3;                       \
        }                                                                         \
    } while (0)

#define DO_MMA(buf)                                                \
    do {                                                           \
        _Pragma("unroll")                                          \
        for (int i = 0; i < 4; i++)                                \
            _Pragma("unroll")                                      \
            for (int j = 0; j < 8; j++)                            \
                MMA_F16(acc[i][j], af[buf][i], bf[buf][j]);        \
    } while (0)

    LDFRAG(0, 0, 0);

#pragma unroll 1
    for (int kt = 0; kt < NKIT; kt++) {
        const int s = kt % STAGES;
        LDFRAG(1, s, 1);
        if (kt + 3 < NKIT) LOAD_STAGE(kt + 3, (kt + 3) % STAGES);
        asm volatile("cp.async.commit_group;\n");
        DO_MMA(0);
        asm volatile("cp.async.wait_group 2;\n");
        __syncthreads();
        LDFRAG(0, (kt + 1) % STAGES, 0);        // last iter: harmless stale read
        DO_MMA(1);
    }

    // ---- epilogue ----
    const int seg = bn >> 10;
    float* outp = ea.out[seg];
    const float* biasp = ea.bias[seg];
    const int lr = lane >> 2;
    const int lc = (lane & 3) * 2;

#pragma unroll
    for (int i = 0; i < 4; i++) {
#pragma unroll
        for (int j = 0; j < 8; j++) {
            const int row = bm + wm * 64 + i * 16 + lr;
            const int col = bn + wn * 64 + j * 8 + lc;
            const int colN = col & (NF - 1);
            float v0 = acc[i][j][0], v1 = acc[i][j][1];
            float v2 = acc[i][j][2], v3 = acc[i][j][3];
            if (biasp) {
                const float b0 = biasp[colN], b1 = biasp[colN + 1];
                v0 = sigf(v0 + b0); v1 = sigf(v1 + b1);
                v2 = sigf(v2 + b0); v3 = sigf(v3 + b1);
            }
            *(float2*)&outp[(size_t)row * NF + colN]       = make_float2(v0, v1);
            *(float2*)&outp[(size_t)(row + 8) * NF + colN] = make_float2(v2, v3);
        }
    }
}

// ---------------------------------------------------------------------------
// fp32 -> fp16 conversions
// ---------------------------------------------------------------------------
__global__ void conv_kernel(const float* __restrict__ in,
                            __half* __restrict__ out, int total4)
{
    int i = blockIdx.x * blockDim.x + threadIdx.x;
    if (i >= total4) return;
    float4 v = ((const float4*)in)[i];
    ((__half2*)out)[2*i]   = __floats2half2_rn(v.x, v.y);
    ((__half2*)out)[2*i+1] = __floats2half2_rn(v.z, v.w);
}

__global__ void conv2_kernel(const float* __restrict__ inA, __half* __restrict__ outA,
                             const float* __restrict__ inB, __half* __restrict__ outB,
                             int total4)
{
    int i = blockIdx.x * blockDim.x + threadIdx.x;
    if (i >= total4) return;
    float4 v = ((const float4*)inA)[i];
    ((__half2*)outA)[2*i]   = __floats2half2_rn(v.x, v.y);
    ((__half2*)outA)[2*i+1] = __floats2half2_rn(v.z, v.w);
    float4 w = ((const float4*)inB)[i];
    ((__half2*)outB)[2*i]   = __floats2half2_rn(w.x, w.y);
    ((__half2*)outB)[2*i+1] = __floats2half2_rn(w.z, w.w);
}

// ---------------------------------------------------------------------------
// Chunked scan, 3 passes. Channel c = b*NF + m; time-major stride NF.
// Pass 1: per (chunk, channel): a = prod r_t, bsum = scan of wi*wig from 0.
// ---------------------------------------------------------------------------
__global__ void scan_p1(void)
{
    const int c  = blockIdx.x * blockDim.x + threadIdx.x;   // channel
    const int ch = blockIdx.y;                              // chunk
    if (c >= NCHAN) return;
    const int b = c >> 10;
    const int m = c & (NF - 1);

    size_t idx = (size_t)b * TT * NF + (size_t)ch * CHT * NF + m;
    float a = 1.0f, bs = 0.0f;
#pragma unroll 8
    for (int t = 0; t < CHT; t++) {
        const float r  = g_r[idx];
        const float xi = g_wi[idx] * g_wig[idx];
        bs = fmaf(bs, r, xi);
        a *= r;
        idx += NF;
    }
    g_sa[ch * NCHAN + c] = a;
    g_sb[ch * NCHAN + c] = bs;
}

// Pass 2: serial combine over 16 chunks per channel; record chunk start h.
__global__ void scan_p2(const float* __restrict__ mem0,
                        float* __restrict__ mem_out)
{
    const int c = blockIdx.x * blockDim.x + threadIdx.x;
    if (c >= NCHAN) return;
    float h = mem0[c];
#pragma unroll
    for (int ch = 0; ch < NCH; ch++) {
        g_hs[ch * NCHAN + c] = h;
        h = fmaf(h, g_sa[ch * NCHAN + c], g_sb[ch * NCHAN + c]);
    }
    mem_out[c] = h;
}

// Pass 3: recompute within chunk from known start h; emit z = softsign(h)*og.
__global__ void scan_p3(void)
{
    const int c  = blockIdx.x * blockDim.x + threadIdx.x;
    const int ch = blockIdx.y;
    if (c >= NCHAN) return;
    const int b = c >> 10;
    const int m = c & (NF - 1);

    float h = g_hs[ch * NCHAN + c];
    size_t idx = (size_t)b * TT * NF + (size_t)ch * CHT * NF + m;
#pragma unroll 8
    for (int t = 0; t < CHT; t++) {
        const float r  = g_r[idx];
        const float xi = g_wi[idx] * g_wig[idx];
        h = fmaf(h, r, xi);
        const float z = (h / (1.0f + fabsf(h))) * g_og[idx];
        g_zh[idx] = __float2half_rn(z);
        idx += NF;
    }
}

// ---------------------------------------------------------------------------
// Launch. Inputs: x, mem, wr_w, wr_b, wi_w, wig_w, wig_b, wog_w, wog_b, wo_w
// Output: y [8,2048,1024] f32 then mem_out [8,1024] f32.
// ---------------------------------------------------------------------------
extern "C" void kernel_launch(void* const* d_in, const int* in_sizes, int n_in,
                              void* d_out, int out_size)
{
    const float* x     = (const float*)d_in[0];
    const float* mem0  = (const float*)d_in[1];
    const float* wr_w  = (const float*)d_in[2];
    const float* wr_b  = (const float*)d_in[3];
    const float* wi_w  = (const float*)d_in[4];
    const float* wig_w = (const float*)d_in[5];
    const float* wig_b = (const float*)d_in[6];
    const float* wog_w = (const float*)d_in[7];
    const float* wog_b = (const float*)d_in[8];
    const float* wo_w  = (const float*)d_in[9];

    float* y       = (float*)d_out;
    float* mem_out = y + (size_t)BT * NF;

    float *p_wi, *p_wig, *p_r, *p_og;
    __half *p_xh, *p_zh, *p_w4, *p_woh;
    cudaGetSymbolAddress((void**)&p_wi,  g_wi);
    cudaGetSymbolAddress((void**)&p_wig, g_wig);
    cudaGetSymbolAddress((void**)&p_r,   g_r);
    cudaGetSymbolAddress((void**)&p_og,  g_og);
    cudaGetSymbolAddress((void**)&p_xh,  g_xh);
    cudaGetSymbolAddress((void**)&p_zh,  g_zh);
    cudaGetSymbolAddress((void**)&p_w4,  g_w4);
    cudaGetSymbolAddress((void**)&p_woh, g_woh);

    const size_t ws = (size_t)NF * NF;

    cudaFuncSetAttribute(hgemm_kernel, cudaFuncAttributeMaxDynamicSharedMemorySize, SMEM_BYTES);

    // 1. conversions: exactly 4 launches so GEMM1 is the 5th launch (ncu window)
    {
        int wt4 = (NF * NF) / 4;
        int wb = (wt4 + 255) / 256;
        conv2_kernel<<<wb, 256>>>(wr_w,  p_w4 + 0 * ws, wi_w,  p_w4 + 1 * ws, wt4);   // 1
        conv2_kernel<<<wb, 256>>>(wig_w, p_w4 + 2 * ws, wog_w, p_w4 + 3 * ws, wt4);   // 2
        conv_kernel<<<wb, 256>>>(wo_w, p_woh, wt4);                                   // 3
        int xt4 = (BT * NF) / 4;
        conv_kernel<<<(xt4 + 255) / 256, 256>>>(x, p_xh, xt4);                        // 4
    }

    // 2. fused input projections: C[16384, 4096]                                     // 5 <- profiled
    {
        EpiArgs ea;
        ea.out[0] = p_r;   ea.bias[0] = wr_b;
        ea.out[1] = p_wi;  ea.bias[1] = nullptr;   // raw (no sigmoid)
        ea.out[2] = p_wig; ea.bias[2] = wig_b;
        ea.out[3] = p_og;  ea.bias[3] = wog_b;
        dim3 grid(4 * NF / BN, BT / BM);   // (32, 128)
        hgemm_kernel<<<grid, 128, SMEM_BYTES>>>(p_xh, p_w4, ea);
    }

    // 3. chunked recurrence scan                                                     // 6,7,8
    {
        dim3 g1(NCHAN / 256, NCH);
        scan_p1<<<g1, 256>>>();
        scan_p2<<<NCHAN / 256, 256>>>(mem0, mem_out);
        scan_p3<<<g1, 256>>>();
    }

    // 4. output projection: y = z @ wo^T                                             // 9
    {
        EpiArgs ea;
        ea.out[0] = y;       ea.bias[0] = nullptr;
        ea.out[1] = nullptr; ea.bias[1] = nullptr;
        ea.out[2] = nullptr; ea.bias[2] = nullptr;
        ea.out[3] = nullptr; ea.bias[3] = nullptr;
        dim3 grid(NF / BN, BT / BM);       // (8, 128)
        hgemm_kernel<<<grid, 128, SMEM_BYTES>>>(p_zh, p_woh, ea);
    }
}